// round 1
// baseline (speedup 1.0000x reference)
#include <cuda_runtime.h>
#include <math.h>

#define BB 2
#define QQ 300
#define TT 300
#define HH 256
#define WW 256
#define PP 12544
#define BK 16
#define NC (PP / BK)          // 784 k-chunks
#define KSPLIT 6
#define CPS ((NC + KSPLIT - 1) / KSPLIT)   // 131

// ------------------------- scratch (static device memory, no runtime alloc) ---
__device__ float g_om[(size_t)BB * QQ * PP];   // sampled pred logits
__device__ float g_sg[(size_t)BB * QQ * PP];   // sigmoid(om)
__device__ float g_tm[(size_t)BB * TT * PP];   // sampled tgt masks
__device__ float g_negsum[BB * QQ];            // sum_p softplus(om)
__device__ float g_ssum[BB * QQ];              // sum_p sigmoid(om)
__device__ float g_tmsum[BB * TT];             // sum_p tm
__device__ float g_pA[(size_t)BB * KSPLIT * QQ * TT];  // partial om.tm
__device__ float g_pS[(size_t)BB * KSPLIT * QQ * TT];  // partial sg.tm
__device__ int2   g_ij[BB * PP];
__device__ float2 g_w [BB * PP];

// ------------------------- kernel 1: per-point bilinear coords ----------------
__global__ void prep_points(const float* __restrict__ pc) {
    int i = blockIdx.x * blockDim.x + threadIdx.x;
    if (i >= BB * PP) return;
    float x = pc[2 * i + 0] * (float)WW - 0.5f;
    float y = pc[2 * i + 1] * (float)HH - 0.5f;
    float x0 = floorf(x), y0 = floorf(y);
    g_ij[i] = make_int2((int)x0, (int)y0);
    g_w[i]  = make_float2(x - x0, y - y0);
}

// ------------------------- kernel 2: point sampling + row sums ----------------
// grid: (QQ+TT, BB), block 1024.  One block = one mask image (256KB), stays L2-hot.
__global__ __launch_bounds__(1024, 1)
void sample_kernel(const float* __restrict__ pred_masks,
                   const float* __restrict__ tgt_masks) {
    int b = blockIdx.y;
    int m = blockIdx.x;
    bool is_pred = (m < QQ);
    int  mi = is_pred ? m : m - QQ;
    const float* img = is_pred ? pred_masks + (size_t)(b * QQ + mi) * HH * WW
                               : tgt_masks  + (size_t)(b * TT + mi) * HH * WW;
    float* dst  = is_pred ? g_om + (size_t)(b * QQ + mi) * PP
                          : g_tm + (size_t)(b * TT + mi) * PP;
    float* sdst = g_sg + (size_t)(b * QQ + mi) * PP;

    const int2*   ij = g_ij + b * PP;
    const float2* wv = g_w  + b * PP;

    float s0 = 0.f, s1 = 0.f;
    for (int p = threadIdx.x; p < PP; p += blockDim.x) {
        int2   c = ij[p];
        float2 w = wv[p];
        int x0 = c.x, y0 = c.y;
        float wx = w.x, wy = w.y;
        // x0 in [-1, W-1], y0 in [-1, H-1]
        int xc0 = x0 < 0 ? 0 : x0;
        int xc1 = (x0 + 1 > WW - 1) ? WW - 1 : x0 + 1;
        int yc0 = y0 < 0 ? 0 : y0;
        int yc1 = (y0 + 1 > HH - 1) ? HH - 1 : y0 + 1;
        float fx0 = (x0 >= 0)      ? 1.f : 0.f;
        float fx1 = (x0 + 1 < WW)  ? 1.f : 0.f;
        float fy0 = (y0 >= 0)      ? 1.f : 0.f;
        float fy1 = (y0 + 1 < HH)  ? 1.f : 0.f;
        const float* r0 = img + yc0 * WW;
        const float* r1 = img + yc1 * WW;
        float v00 = r0[xc0] * (fx0 * fy0);
        float v01 = r0[xc1] * (fx1 * fy0);
        float v10 = r1[xc0] * (fx0 * fy1);
        float v11 = r1[xc1] * (fx1 * fy1);
        float val = v00 * (1.f - wy) * (1.f - wx) + v01 * (1.f - wy) * wx
                  + v10 * wy * (1.f - wx)         + v11 * wy * wx;
        dst[p] = val;
        if (is_pred) {
            float sg = 1.f / (1.f + __expf(-val));
            sdst[p] = sg;
            s1 += sg;
            s0 += fmaxf(val, 0.f) + log1pf(__expf(-fabsf(val)));  // softplus
        } else {
            s0 += val;
        }
    }
    // block reduction (s0, s1)
    #pragma unroll
    for (int o = 16; o > 0; o >>= 1) {
        s0 += __shfl_down_sync(0xffffffffu, s0, o);
        s1 += __shfl_down_sync(0xffffffffu, s1, o);
    }
    __shared__ float r0s[32], r1s[32];
    int wid = threadIdx.x >> 5, lid = threadIdx.x & 31;
    if (lid == 0) { r0s[wid] = s0; r1s[wid] = s1; }
    __syncthreads();
    if (wid == 0) {
        int nw = blockDim.x >> 5;
        s0 = (lid < nw) ? r0s[lid] : 0.f;
        s1 = (lid < nw) ? r1s[lid] : 0.f;
        #pragma unroll
        for (int o = 16; o > 0; o >>= 1) {
            s0 += __shfl_down_sync(0xffffffffu, s0, o);
            s1 += __shfl_down_sync(0xffffffffu, s1, o);
        }
        if (lid == 0) {
            if (is_pred) { g_negsum[b * QQ + mi] = s0; g_ssum[b * QQ + mi] = s1; }
            else         { g_tmsum[b * TT + mi] = s0; }
        }
    }
}

// ------------------------- kernel 3: dual-accumulator split-K GEMM ------------
// C_A[q,t] = sum_p om[q,p]*tm[t,p] ; C_S[q,t] = sum_p sg[q,p]*tm[t,p]
// tiles 64x64, BK=16, 256 threads, each thread 4x4 outputs per accumulator.
__global__ __launch_bounds__(256, 2)
void gemm_kernel() {
    __shared__ float As[BK][68], Ss[BK][68], Bs[BK][68];
    int b  = blockIdx.z;
    int ks = blockIdx.y;
    int tq = blockIdx.x / 5, tt = blockIdx.x % 5;
    int q0 = tq * 64, t0 = tt * 64;
    int tid = threadIdx.x;
    int tx = tid & 15, ty = tid >> 4;
    int lr = tid >> 2;          // 0..63  (row within tile)
    int lc = (tid & 3) * 4;     // 0,4,8,12 (k offset within chunk)
    int qr = q0 + lr; if (qr > QQ - 1) qr = QQ - 1;
    int tr = t0 + lr; if (tr > TT - 1) tr = TT - 1;
    const float* Aptr = g_om + (size_t)(b * QQ + qr) * PP;
    const float* Sptr = g_sg + (size_t)(b * QQ + qr) * PP;
    const float* Bptr = g_tm + (size_t)(b * TT + tr) * PP;

    int cs = ks * CPS;
    int ce = cs + CPS; if (ce > NC) ce = NC;

    float accA[4][4] = {{0.f}}, accS[4][4] = {{0.f}};

    for (int c = cs; c < ce; c++) {
        int kk = c * BK + lc;
        float4 av = *(const float4*)(Aptr + kk);
        float4 sv = *(const float4*)(Sptr + kk);
        float4 bv = *(const float4*)(Bptr + kk);
        __syncthreads();
        As[lc + 0][lr] = av.x; As[lc + 1][lr] = av.y; As[lc + 2][lr] = av.z; As[lc + 3][lr] = av.w;
        Ss[lc + 0][lr] = sv.x; Ss[lc + 1][lr] = sv.y; Ss[lc + 2][lr] = sv.z; Ss[lc + 3][lr] = sv.w;
        Bs[lc + 0][lr] = bv.x; Bs[lc + 1][lr] = bv.y; Bs[lc + 2][lr] = bv.z; Bs[lc + 3][lr] = bv.w;
        __syncthreads();
        #pragma unroll
        for (int k = 0; k < BK; k++) {
            float4 a4 = *(const float4*)&As[k][ty * 4];
            float4 s4 = *(const float4*)&Ss[k][ty * 4];
            float4 b4 = *(const float4*)&Bs[k][tx * 4];
            float ar[4] = {a4.x, a4.y, a4.z, a4.w};
            float sr[4] = {s4.x, s4.y, s4.z, s4.w};
            float br[4] = {b4.x, b4.y, b4.z, b4.w};
            #pragma unroll
            for (int i = 0; i < 4; i++)
                #pragma unroll
                for (int j = 0; j < 4; j++) {
                    accA[i][j] += ar[i] * br[j];
                    accS[i][j] += sr[i] * br[j];
                }
        }
    }
    #pragma unroll
    for (int i = 0; i < 4; i++)
        #pragma unroll
        for (int j = 0; j < 4; j++) {
            int q = q0 + ty * 4 + i;
            int t = t0 + tx * 4 + j;
            if (q < QQ && t < TT) {
                size_t o = (((size_t)(b * KSPLIT + ks) * QQ) + q) * TT + t;
                g_pA[o] = accA[i][j];
                g_pS[o] = accS[i][j];
            }
        }
}

// ------------------------- kernel 4: reduce partials + box costs --------------
__global__ void finalize_kernel(const float* __restrict__ pred_boxes,
                                const float* __restrict__ tgt_boxes,
                                float* __restrict__ out) {
    int idx = blockIdx.x * blockDim.x + threadIdx.x;
    if (idx >= BB * QQ * TT) return;
    int t = idx % TT;
    int q = (idx / TT) % QQ;
    int b = idx / (QQ * TT);

    float A = 0.f, S = 0.f;
    #pragma unroll
    for (int ks = 0; ks < KSPLIT; ks++) {
        size_t o = (((size_t)(b * KSPLIT + ks) * QQ) + q) * TT + t;
        A += g_pA[o];
        S += g_pS[o];
    }
    float cost_mask = (g_negsum[b * QQ + q] - A) * (1.0f / (float)PP);
    float cost_dice = 1.f - (2.f * S + 1.f) / (g_ssum[b * QQ + q] + g_tmsum[b * TT + t] + 1.f);

    const float* pq = pred_boxes + (size_t)(b * QQ + q) * 4;
    const float* pt = tgt_boxes  + (size_t)(b * TT + t) * 4;
    float l1 = fabsf(pq[0] - pt[0]) + fabsf(pq[1] - pt[1])
             + fabsf(pq[2] - pt[2]) + fabsf(pq[3] - pt[3]);

    float ax0 = pq[0] - 0.5f * pq[2], ay0 = pq[1] - 0.5f * pq[3];
    float ax1 = pq[0] + 0.5f * pq[2], ay1 = pq[1] + 0.5f * pq[3];
    float bx0 = pt[0] - 0.5f * pt[2], by0 = pt[1] - 0.5f * pt[3];
    float bx1 = pt[0] + 0.5f * pt[2], by1 = pt[1] + 0.5f * pt[3];
    float area_a = (ax1 - ax0) * (ay1 - ay0);
    float area_b = (bx1 - bx0) * (by1 - by0);
    float iw = fminf(ax1, bx1) - fmaxf(ax0, bx0);
    float ih = fminf(ay1, by1) - fmaxf(ay0, by0);
    iw = fmaxf(iw, 0.f); ih = fmaxf(ih, 0.f);
    float inter = iw * ih;
    float uni = area_a + area_b - inter;
    float iou = inter / uni;
    float ew = fmaxf(ax1, bx1) - fminf(ax0, bx0);
    float eh = fmaxf(ay1, by1) - fminf(ay0, by0);
    ew = fmaxf(ew, 0.f); eh = fmaxf(eh, 0.f);
    float ae = ew * eh;
    float giou = iou - (ae - uni) / ae;

    out[idx] = 5.f * (cost_mask + cost_dice + l1) - 2.f * giou;
}

// ------------------------- launch --------------------------------------------
extern "C" void kernel_launch(void* const* d_in, const int* in_sizes, int n_in,
                              void* d_out, int out_size) {
    const float* pred_masks   = (const float*)d_in[0];
    const float* tgt_masks    = (const float*)d_in[1];
    const float* pred_boxes   = (const float*)d_in[2];
    const float* tgt_boxes    = (const float*)d_in[3];
    const float* point_coords = (const float*)d_in[4];

    prep_points<<<(BB * PP + 255) / 256, 256>>>(point_coords);
    sample_kernel<<<dim3(QQ + TT, BB), 1024>>>(pred_masks, tgt_masks);
    gemm_kernel<<<dim3(25, KSPLIT, BB), 256>>>();
    finalize_kernel<<<(BB * QQ * TT + 255) / 256, 256>>>(pred_boxes, tgt_boxes,
                                                          (float*)d_out);
}

// round 3
// speedup vs baseline: 1.8511x; 1.8511x over previous
#include <cuda_runtime.h>
#include <cuda_bf16.h>
#include <cstdint>
#include <math.h>

#define BB 2
#define QQ 300
#define TT 300
#define HH 256
#define WW 256
#define PP 12544

// ---- GEMM config (mma.sync bf16, HMMA path) ----
#define MT 128                 // CTA M tile (Q)
#define NT 64                  // CTA N tile (T)
#define BK 64                  // bf16 K elems per chunk (128 bytes/row)
#define CHB (BK * 2)           // 128 bytes per row per chunk
#define NCH (PP / BK)          // 196 chunks
#define KS 7                   // split-K
#define CPK (NCH / KS)         // 28 chunks per split
#define QT 3                   // ceil(300/128)
#define TTL 5                  // ceil(300/64)
#define PADQ 384
#define PADT 320

// smem: stage = A(16KB) + S(16KB) + B(8KB) = 40960B, double buffered
#define SM_A 0
#define SM_S 16384
#define SM_B 32768
#define STAGE_B 40960
#define SM_TOTAL (2 * STAGE_B)

// ------------------------- scratch ------------------------------------------
__device__ __nv_bfloat16 g_om[(size_t)BB * QQ * PP];
__device__ __nv_bfloat16 g_sg[(size_t)BB * QQ * PP];
__device__ __nv_bfloat16 g_tm[(size_t)BB * TT * PP];
__device__ float g_negsum[BB * QQ];
__device__ float g_ssum[BB * QQ];
__device__ float g_tmsum[BB * TT];
__device__ float g_pA[(size_t)BB * KS * PADQ * PADT];
__device__ float g_pS[(size_t)BB * KS * PADQ * PADT];
__device__ int2   g_ij[BB * PP];
__device__ float2 g_w [BB * PP];

// ------------------------- PTX helpers --------------------------------------
__device__ __forceinline__ uint32_t smem_u32(const void* p) {
    uint32_t a;
    asm("{ .reg .u64 t; cvta.to.shared.u64 t, %1; cvt.u32.u64 %0, t; }" : "=r"(a) : "l"(p));
    return a;
}
__device__ __forceinline__ void cp16(uint32_t s, const void* g) {
    asm volatile("cp.async.cg.shared.global [%0], [%1], 16;" :: "r"(s), "l"(g));
}
#define CP_COMMIT() asm volatile("cp.async.commit_group;" ::: "memory")
#define CP_WAIT(n)  asm volatile("cp.async.wait_group %0;" :: "n"(n) : "memory")

__device__ __forceinline__ uint32_t sw128(uint32_t off) { return off ^ ((off >> 3) & 0x70); }

__device__ __forceinline__ void ldsm4(uint32_t& r0, uint32_t& r1, uint32_t& r2, uint32_t& r3,
                                      uint32_t addr) {
    asm volatile("ldmatrix.sync.aligned.m8n8.x4.shared.b16 {%0,%1,%2,%3}, [%4];"
                 : "=r"(r0), "=r"(r1), "=r"(r2), "=r"(r3) : "r"(addr));
}
__device__ __forceinline__ void mma16816(float* c, const uint32_t* a, uint32_t b0, uint32_t b1) {
    asm volatile("mma.sync.aligned.m16n8k16.row.col.f32.bf16.bf16.f32 "
                 "{%0,%1,%2,%3}, {%4,%5,%6,%7}, {%8,%9}, {%0,%1,%2,%3};"
                 : "+f"(c[0]), "+f"(c[1]), "+f"(c[2]), "+f"(c[3])
                 : "r"(a[0]), "r"(a[1]), "r"(a[2]), "r"(a[3]), "r"(b0), "r"(b1));
}

// ------------------------- kernel 1: per-point bilinear coords ----------------
__global__ void prep_points(const float* __restrict__ pc) {
    int i = blockIdx.x * blockDim.x + threadIdx.x;
    if (i >= BB * PP) return;
    float x = pc[2 * i + 0] * (float)WW - 0.5f;
    float y = pc[2 * i + 1] * (float)HH - 0.5f;
    float x0 = floorf(x), y0 = floorf(y);
    g_ij[i] = make_int2((int)x0, (int)y0);
    g_w[i]  = make_float2(x - x0, y - y0);
}

// ------------------------- kernel 2: point sampling + row sums ----------------
__global__ __launch_bounds__(1024, 1)
void sample_kernel(const float* __restrict__ pred_masks,
                   const float* __restrict__ tgt_masks) {
    int b = blockIdx.y;
    int m = blockIdx.x;
    bool is_pred = (m < QQ);
    int  mi = is_pred ? m : m - QQ;
    const float* img = is_pred ? pred_masks + (size_t)(b * QQ + mi) * HH * WW
                               : tgt_masks  + (size_t)(b * TT + mi) * HH * WW;
    __nv_bfloat16* dst  = is_pred ? g_om + (size_t)(b * QQ + mi) * PP
                                  : g_tm + (size_t)(b * TT + mi) * PP;
    __nv_bfloat16* sdst = g_sg + (size_t)(b * QQ + mi) * PP;

    const int2*   ij = g_ij + b * PP;
    const float2* wv = g_w  + b * PP;

    float s0 = 0.f, s1 = 0.f;
    for (int p = threadIdx.x; p < PP; p += blockDim.x) {
        int2   c = ij[p];
        float2 w = wv[p];
        int x0 = c.x, y0 = c.y;
        float wx = w.x, wy = w.y;
        int xc0 = x0 < 0 ? 0 : x0;
        int xc1 = (x0 + 1 > WW - 1) ? WW - 1 : x0 + 1;
        int yc0 = y0 < 0 ? 0 : y0;
        int yc1 = (y0 + 1 > HH - 1) ? HH - 1 : y0 + 1;
        float fx0 = (x0 >= 0)     ? 1.f : 0.f;
        float fx1 = (x0 + 1 < WW) ? 1.f : 0.f;
        float fy0 = (y0 >= 0)     ? 1.f : 0.f;
        float fy1 = (y0 + 1 < HH) ? 1.f : 0.f;
        const float* r0 = img + yc0 * WW;
        const float* r1 = img + yc1 * WW;
        float v00 = r0[xc0] * (fx0 * fy0);
        float v01 = r0[xc1] * (fx1 * fy0);
        float v10 = r1[xc0] * (fx0 * fy1);
        float v11 = r1[xc1] * (fx1 * fy1);
        float val = v00 * (1.f - wy) * (1.f - wx) + v01 * (1.f - wy) * wx
                  + v10 * wy * (1.f - wx)         + v11 * wy * wx;
        dst[p] = __float2bfloat16(val);
        if (is_pred) {
            float sg = 1.f / (1.f + __expf(-val));
            sdst[p] = __float2bfloat16(sg);
            s1 += sg;
            s0 += fmaxf(val, 0.f) + log1pf(__expf(-fabsf(val)));
        } else {
            s0 += val;
        }
    }
    #pragma unroll
    for (int o = 16; o > 0; o >>= 1) {
        s0 += __shfl_down_sync(0xffffffffu, s0, o);
        s1 += __shfl_down_sync(0xffffffffu, s1, o);
    }
    __shared__ float r0s[32], r1s[32];
    int wid = threadIdx.x >> 5, lid = threadIdx.x & 31;
    if (lid == 0) { r0s[wid] = s0; r1s[wid] = s1; }
    __syncthreads();
    if (wid == 0) {
        int nw = blockDim.x >> 5;
        s0 = (lid < nw) ? r0s[lid] : 0.f;
        s1 = (lid < nw) ? r1s[lid] : 0.f;
        #pragma unroll
        for (int o = 16; o > 0; o >>= 1) {
            s0 += __shfl_down_sync(0xffffffffu, s0, o);
            s1 += __shfl_down_sync(0xffffffffu, s1, o);
        }
        if (lid == 0) {
            if (is_pred) { g_negsum[b * QQ + mi] = s0; g_ssum[b * QQ + mi] = s1; }
            else         { g_tmsum[b * TT + mi] = s0; }
        }
    }
}

// ------------------------- kernel 3: dual bf16 mma.sync GEMM (split-K) --------
// cA[q,t] = sum_p om*tm ; cS[q,t] = sum_p sg*tm.
// CTA 128x64 tile, 8 warps (4x2), warp 32x32 per GEMM, BK=64, double-buffered cp.async.
__global__ __launch_bounds__(256)
void gemm_mma_kernel() {
    extern __shared__ char smem[];
    uint32_t sb = smem_u32(smem);
    int tid = threadIdx.x;
    int wid = tid >> 5, lane = tid & 31;

    int b  = blockIdx.z;
    int ks = blockIdx.y;
    int tq = blockIdx.x / TTL, tt = blockIdx.x % TTL;
    int q0 = tq * MT, t0 = tt * NT;

    // warp tile: 4 warps in M, 2 in N
    int wm0 = (wid >> 1) * 32;
    int wn0 = (wid & 1) * 32;

    // global load mapping: A/S 128 rows x 128B (thread: row=tid/2, 64B half);
    //                      B 64 rows x 128B (thread: row=tid/4, 32B quarter)
    int arow = tid >> 1, ahalf = tid & 1;
    int brow = tid >> 2, bqt = tid & 3;
    int qr = q0 + arow; if (qr > QQ - 1) qr = QQ - 1;
    int tr = t0 + brow; if (tr > TT - 1) tr = TT - 1;
    const char* Ab = (const char*)(g_om + (size_t)(b * QQ + qr) * PP);
    const char* Sb = (const char*)(g_sg + (size_t)(b * QQ + qr) * PP);
    const char* Bb = (const char*)(g_tm + (size_t)(b * TT + tr) * PP);

    int cs = ks * CPK;

    float cA[2][4][4] = {}, cS[2][4][4] = {};

    // prologue load chunk 0 -> stage 0
    {
        uint32_t st = sb;
        size_t g = (size_t)cs * CHB;
        #pragma unroll
        for (int u = 0; u < 4; u++) {
            uint32_t inrow = ahalf * 64 + u * 16;
            uint32_t sw = sw128((uint32_t)arow * 128 + inrow);
            cp16(st + SM_A + sw, Ab + g + inrow);
            cp16(st + SM_S + sw, Sb + g + inrow);
        }
        #pragma unroll
        for (int u = 0; u < 2; u++) {
            uint32_t inrow = bqt * 32 + u * 16;
            uint32_t sw = sw128((uint32_t)brow * 128 + inrow);
            cp16(st + SM_B + sw, Bb + g + inrow);
        }
        CP_COMMIT();
    }

    for (int c = 0; c < CPK; c++) {
        int stg = c & 1;
        if (c + 1 < CPK) {
            uint32_t st = sb + ((c + 1) & 1) * STAGE_B;
            size_t g = (size_t)(cs + c + 1) * CHB;
            #pragma unroll
            for (int u = 0; u < 4; u++) {
                uint32_t inrow = ahalf * 64 + u * 16;
                uint32_t sw = sw128((uint32_t)arow * 128 + inrow);
                cp16(st + SM_A + sw, Ab + g + inrow);
                cp16(st + SM_S + sw, Sb + g + inrow);
            }
            #pragma unroll
            for (int u = 0; u < 2; u++) {
                uint32_t inrow = bqt * 32 + u * 16;
                uint32_t sw = sw128((uint32_t)brow * 128 + inrow);
                cp16(st + SM_B + sw, Bb + g + inrow);
            }
            CP_COMMIT();
            CP_WAIT(1);
        } else {
            CP_WAIT(0);
        }
        __syncthreads();

        uint32_t stA = sb + stg * STAGE_B + SM_A;
        uint32_t stS = sb + stg * STAGE_B + SM_S;
        uint32_t stB = sb + stg * STAGE_B + SM_B;

        #pragma unroll
        for (int kk = 0; kk < 4; kk++) {        // 4 k16 steps per BK=64 chunk
            uint32_t af[2][4], sf[2][4], bf[4][2];
            // A / S fragments: two m16 tiles
            #pragma unroll
            for (int mt = 0; mt < 2; mt++) {
                uint32_t row = wm0 + mt * 16 + (lane & 15);
                uint32_t inrow = kk * 32 + (lane >> 4) * 16;
                uint32_t sw = sw128(row * 128 + inrow);
                ldsm4(af[mt][0], af[mt][1], af[mt][2], af[mt][3], stA + sw);
                ldsm4(sf[mt][0], sf[mt][1], sf[mt][2], sf[mt][3], stS + sw);
            }
            // B fragments: 32 n-cols = two x4 loads (each covers two n8 tiles)
            #pragma unroll
            for (int nb = 0; nb < 2; nb++) {
                uint32_t row = wn0 + nb * 16 + (lane & 15);
                uint32_t inrow = kk * 32 + (lane >> 4) * 16;
                uint32_t sw = sw128(row * 128 + inrow);
                uint32_t r0, r1, r2, r3;
                ldsm4(r0, r1, r2, r3, stB + sw);
                bf[nb * 2 + 0][0] = r0; bf[nb * 2 + 0][1] = r2;
                bf[nb * 2 + 1][0] = r1; bf[nb * 2 + 1][1] = r3;
            }
            #pragma unroll
            for (int mt = 0; mt < 2; mt++)
                #pragma unroll
                for (int nt = 0; nt < 4; nt++) {
                    mma16816(cA[mt][nt], af[mt], bf[nt][0], bf[nt][1]);
                    mma16816(cS[mt][nt], sf[mt], bf[nt][0], bf[nt][1]);
                }
        }
        __syncthreads();
    }

    // epilogue: write partials (padded, no bounds checks; garbage rows ignored)
    int rbase = q0 + wm0 + (lane >> 2);
    int cbase = t0 + wn0 + (lane & 3) * 2;
    size_t pbase = (size_t)(b * KS + ks) * PADQ * PADT;
    #pragma unroll
    for (int mt = 0; mt < 2; mt++)
        #pragma unroll
        for (int nt = 0; nt < 4; nt++) {
            size_t o = pbase + (size_t)(rbase + mt * 16) * PADT + (cbase + nt * 8);
            *(float2*)(g_pA + o)            = make_float2(cA[mt][nt][0], cA[mt][nt][1]);
            *(float2*)(g_pA + o + 8 * PADT) = make_float2(cA[mt][nt][2], cA[mt][nt][3]);
            *(float2*)(g_pS + o)            = make_float2(cS[mt][nt][0], cS[mt][nt][1]);
            *(float2*)(g_pS + o + 8 * PADT) = make_float2(cS[mt][nt][2], cS[mt][nt][3]);
        }
}

// ------------------------- kernel 4: reduce partials + box costs --------------
__global__ void finalize_kernel(const float* __restrict__ pred_boxes,
                                const float* __restrict__ tgt_boxes,
                                float* __restrict__ out) {
    int idx = blockIdx.x * blockDim.x + threadIdx.x;
    if (idx >= BB * QQ * TT) return;
    int t = idx % TT;
    int q = (idx / TT) % QQ;
    int b = idx / (QQ * TT);

    float A = 0.f, S = 0.f;
    #pragma unroll
    for (int ks = 0; ks < KS; ks++) {
        size_t o = ((size_t)(b * KS + ks) * PADQ + q) * PADT + t;
        A += g_pA[o];
        S += g_pS[o];
    }
    float cost_mask = (g_negsum[b * QQ + q] - A) * (1.0f / (float)PP);
    float cost_dice = 1.f - (2.f * S + 1.f) / (g_ssum[b * QQ + q] + g_tmsum[b * TT + t] + 1.f);

    const float* pq = pred_boxes + (size_t)(b * QQ + q) * 4;
    const float* pt = tgt_boxes  + (size_t)(b * TT + t) * 4;
    float l1 = fabsf(pq[0] - pt[0]) + fabsf(pq[1] - pt[1])
             + fabsf(pq[2] - pt[2]) + fabsf(pq[3] - pt[3]);

    float ax0 = pq[0] - 0.5f * pq[2], ay0 = pq[1] - 0.5f * pq[3];
    float ax1 = pq[0] + 0.5f * pq[2], ay1 = pq[1] + 0.5f * pq[3];
    float bx0 = pt[0] - 0.5f * pt[2], by0 = pt[1] - 0.5f * pt[3];
    float bx1 = pt[0] + 0.5f * pt[2], by1 = pt[1] + 0.5f * pt[3];
    float area_a = (ax1 - ax0) * (ay1 - ay0);
    float area_b = (bx1 - bx0) * (by1 - by0);
    float iw = fmaxf(fminf(ax1, bx1) - fmaxf(ax0, bx0), 0.f);
    float ih = fmaxf(fminf(ay1, by1) - fmaxf(ay0, by0), 0.f);
    float inter = iw * ih;
    float uni = area_a + area_b - inter;
    float iou = inter / uni;
    float ew = fmaxf(fmaxf(ax1, bx1) - fminf(ax0, bx0), 0.f);
    float eh = fmaxf(fmaxf(ay1, by1) - fminf(ay0, by0), 0.f);
    float ae = ew * eh;
    float giou = iou - (ae - uni) / ae;

    out[idx] = 5.f * (cost_mask + cost_dice + l1) - 2.f * giou;
}

// ------------------------- launch --------------------------------------------
extern "C" void kernel_launch(void* const* d_in, const int* in_sizes, int n_in,
                              void* d_out, int out_size) {
    const float* pred_masks   = (const float*)d_in[0];
    const float* tgt_masks    = (const float*)d_in[1];
    const float* pred_boxes   = (const float*)d_in[2];
    const float* tgt_boxes    = (const float*)d_in[3];
    const float* point_coords = (const float*)d_in[4];

    cudaFuncSetAttribute(gemm_mma_kernel, cudaFuncAttributeMaxDynamicSharedMemorySize, SM_TOTAL);

    prep_points<<<(BB * PP + 255) / 256, 256>>>(point_coords);
    sample_kernel<<<dim3(QQ + TT, BB), 1024>>>(pred_masks, tgt_masks);
    gemm_mma_kernel<<<dim3(QT * TTL, KS, BB), 256, SM_TOTAL>>>();
    finalize_kernel<<<(BB * QQ * TT + 255) / 256, 256>>>(pred_boxes, tgt_boxes,
                                                          (float*)d_out);
}